// round 5
// baseline (speedup 1.0000x reference)
#include <cuda_runtime.h>
#include <cstdint>

// ============================ problem constants ============================
static constexpr int E_  = 8;
static constexpr int M_  = 1024;
static constexpr int H_  = 2048;   // K of GEMM1, N of GEMM2
static constexpr int I2_ = 4096;   // w1 out cols (gate/up interleaved)
static constexpr int IN_ = 2048;   // intermediate = I2/2 = K of GEMM2
static constexpr int KDIM = 2048;  // K of both GEMMs

static constexpr int TM = 128, TN = 128, KC = 32;
static constexpr int NSTG = 3;
static constexpr int NIT = KDIM / KC;          // 64

// SMEM float strides chosen for conflict-free fragment loads:
//  A[m][k]  stride 36: bank = (4m + k) % 32  -> unique over (g in 0..7, l4 in 0..3)
//  B[k][n]  stride 136: bank = (8k + n) % 32 -> unique over (l4 in 0..3, g in 0..7)
static constexpr int ASTR = 36;
static constexpr int BSTR = 136;
static constexpr int A_FLOATS = TM * ASTR;     // 4608
static constexpr int B_FLOATS = KC * BSTR;     // 4352
static constexpr int STGF = A_FLOATS + B_FLOATS;          // 8960 floats
static constexpr int SMEM_TOTAL = NSTG * STGF * 4;        // 107520 B

// ============================ device scratch ============================
__device__ float g_xr [E_ * M_  * KDIM];   // tf32-rounded X        [e][m][k]
__device__ float g_w1r[E_ * KDIM * I2_];   // tf32-rounded w1       [e][k][n]
__device__ float g_w2r[E_ * IN_  * H_ ];   // tf32-rounded w2       [e][k][n]
__device__ float g_act[E_ * M_  * IN_];    // activation (tf32)     [e][m][i]

// ============================ helpers ============================
__device__ __forceinline__ uint32_t smem_u32(const void* p) {
    uint32_t a;
    asm("{ .reg .u64 t; cvta.to.shared.u64 t, %1; cvt.u32.u64 %0, t; }" : "=r"(a) : "l"(p));
    return a;
}

// round fp32 -> tf32 (round-to-nearest-even-ish: half-up + sticky lsb)
__device__ __forceinline__ float rtf32(float x) {
    uint32_t u = __float_as_uint(x);
    u = (u + 0xFFFu + ((u >> 13) & 1u)) & 0xFFFFE000u;
    return __uint_as_float(u);
}

__device__ __forceinline__ void cpa16(uint32_t s, const float* g) {
    asm volatile("cp.async.cg.shared.global [%0], [%1], 16;" :: "r"(s), "l"(g));
}
#define CP_COMMIT() asm volatile("cp.async.commit_group;" ::: "memory")
#define CP_WAIT1()  asm volatile("cp.async.wait_group 1;" ::: "memory")

// m16n8k8 tf32 MMA, D += A*B (accumulate in place)
__device__ __forceinline__ void mma8(float* d, const uint32_t* a, const uint32_t* b) {
    asm volatile(
        "mma.sync.aligned.m16n8k8.row.col.f32.tf32.tf32.f32 "
        "{%0,%1,%2,%3},{%4,%5,%6,%7},{%8,%9},{%0,%1,%2,%3};"
        : "+f"(d[0]), "+f"(d[1]), "+f"(d[2]), "+f"(d[3])
        : "r"(a[0]), "r"(a[1]), "r"(a[2]), "r"(a[3]), "r"(b[0]), "r"(b[1]));
}

__device__ __forceinline__ float swiglu(float gate, float up) {
    gate = fminf(gate, 7.0f);
    up   = fminf(fmaxf(up, -7.0f), 7.0f);
    float glu = gate * (1.0f / (1.0f + __expf(-1.702f * gate)));
    return (up + 1.0f) * glu;
}

// ============================ prep: tf32 rounding ============================
__global__ __launch_bounds__(256) void round_copy(const float* __restrict__ src,
                                                  int sel, size_t n4) {
    float* dst = (sel == 0) ? g_xr : (sel == 1) ? g_w1r : g_w2r;
    const float4* s4 = (const float4*)src;
    float4* d4 = (float4*)dst;
    for (size_t i = (size_t)blockIdx.x * blockDim.x + threadIdx.x; i < n4;
         i += (size_t)gridDim.x * blockDim.x) {
        float4 v = s4[i];
        v.x = rtf32(v.x); v.y = rtf32(v.y); v.z = rtf32(v.z); v.w = rtf32(v.w);
        d4[i] = v;
    }
}

// ============================ GEMM ============================
// MODE 0: act = swiglu(X @ w1 + b1)  -> g_act   (N total = 4096)
// MODE 1: out = act @ w2 + b2                    (N total = 2048)
template <int MODE>
__global__ __launch_bounds__(256) void gemm_mma(const float* __restrict__ bias,
                                                float* __restrict__ outp) {
    constexpr int NTOT = (MODE == 0) ? I2_ : H_;
    extern __shared__ __align__(16) float sm[];
    const uint32_t sb = smem_u32(sm);

    const int tid = threadIdx.x;
    const int wid = tid >> 5, lane = tid & 31;
    const int wm = wid >> 2, wn = wid & 3;     // 2 x 4 warp grid
    const int g = lane >> 2, l4 = lane & 3;
    const int e = blockIdx.z;
    const int m0 = blockIdx.y * TM, n0 = blockIdx.x * TN;

    const float* Ae = ((MODE == 0) ? g_xr : g_act) + (size_t)e * M_ * KDIM;
    const float* Be = ((MODE == 0) ? g_w1r : g_w2r) + (size_t)e * KDIM * NTOT;

    float acc[4][4][4] = {};

    // per-thread cp.async chunk coordinates (4 chunks A + 4 chunks B per stage)
    const int ar = tid >> 3, ac = (tid & 7) * 4;     // A: rows 0..31 (+32p), 8 chunks/row
    const int br = tid >> 5, bc = (tid & 31) * 4;    // B: rows 0..7 (+8p), 32 chunks/row

    auto load_stage = [&](int s, int k0) {
        uint32_t abase = sb + (uint32_t)(s * STGF) * 4u;
        uint32_t bbase = abase + (uint32_t)A_FLOATS * 4u;
#pragma unroll
        for (int p = 0; p < 4; p++) {
            int r = ar + p * 32;
            cpa16(abase + (uint32_t)(r * ASTR + ac) * 4u,
                  Ae + (size_t)(m0 + r) * KDIM + k0 + ac);
        }
#pragma unroll
        for (int p = 0; p < 4; p++) {
            int r = br + p * 8;
            cpa16(bbase + (uint32_t)(r * BSTR + bc) * 4u,
                  Be + (size_t)(k0 + r) * NTOT + n0 + bc);
        }
    };

    // prologue: stages 0 and 1
    load_stage(0, 0);      CP_COMMIT();
    load_stage(1, KC);     CP_COMMIT();

    for (int i = 0; i < NIT; i++) {
        CP_WAIT1();              // stage i resident
        __syncthreads();         // everyone done with stage (i-1) & sees stage i
        if (i + 2 < NIT) { load_stage((i + 2) % NSTG, (i + 2) * KC); }
        CP_COMMIT();             // keep group count uniform (empty at tail)

        const float* As = sm + (i % NSTG) * STGF;
        const float* Bs = As + A_FLOATS;

#pragma unroll
        for (int ks = 0; ks < 4; ks++) {
            const int k = ks * 8;
            uint32_t af[4][4], bf[4][2];
#pragma unroll
            for (int mt = 0; mt < 4; mt++) {
                int r = wm * 64 + mt * 16 + g;
                af[mt][0] = __float_as_uint(As[r * ASTR + k + l4]);
                af[mt][1] = __float_as_uint(As[(r + 8) * ASTR + k + l4]);
                af[mt][2] = __float_as_uint(As[r * ASTR + k + l4 + 4]);
                af[mt][3] = __float_as_uint(As[(r + 8) * ASTR + k + l4 + 4]);
            }
#pragma unroll
            for (int nt = 0; nt < 4; nt++) {
                int c = wn * 32 + nt * 8 + g;
                bf[nt][0] = __float_as_uint(Bs[(k + l4) * BSTR + c]);
                bf[nt][1] = __float_as_uint(Bs[(k + l4 + 4) * BSTR + c]);
            }
#pragma unroll
            for (int mt = 0; mt < 4; mt++)
#pragma unroll
                for (int nt = 0; nt < 4; nt++)
                    mma8(acc[mt][nt], af[mt], bf[nt]);
        }
    }

    // ============================ epilogue ============================
#pragma unroll
    for (int mt = 0; mt < 4; mt++) {
#pragma unroll
        for (int nt = 0; nt < 4; nt++) {
            int mrow = m0 + wm * 64 + mt * 16 + g;
            int ncol = n0 + wn * 32 + nt * 8 + 2 * l4;
            float2 bv = *(const float2*)&bias[(size_t)e * NTOT + ncol];
            if (MODE == 0) {
                // (even, odd) col pair = (gate, up)
                float a0 = swiglu(acc[mt][nt][0] + bv.x, acc[mt][nt][1] + bv.y);
                float a1 = swiglu(acc[mt][nt][2] + bv.x, acc[mt][nt][3] + bv.y);
                int io = ncol >> 1;
                g_act[((size_t)e * M_ + mrow)     * IN_ + io] = rtf32(a0);
                g_act[((size_t)e * M_ + mrow + 8) * IN_ + io] = rtf32(a1);
            } else {
                float2 v0 = make_float2(acc[mt][nt][0] + bv.x, acc[mt][nt][1] + bv.y);
                float2 v1 = make_float2(acc[mt][nt][2] + bv.x, acc[mt][nt][3] + bv.y);
                *(float2*)&outp[((size_t)e * M_ + mrow)     * H_ + ncol] = v0;
                *(float2*)&outp[((size_t)e * M_ + mrow + 8) * H_ + ncol] = v1;
            }
        }
    }
}

// ============================ launch ============================
extern "C" void kernel_launch(void* const* d_in, const int* in_sizes, int n_in,
                              void* d_out, int out_size) {
    const float* x  = (const float*)d_in[0];
    const float* w1 = (const float*)d_in[1];
    const float* b1 = (const float*)d_in[2];
    const float* w2 = (const float*)d_in[3];
    const float* b2 = (const float*)d_in[4];
    float* out = (float*)d_out;

    cudaFuncSetAttribute(gemm_mma<0>, cudaFuncAttributeMaxDynamicSharedMemorySize, SMEM_TOTAL);
    cudaFuncSetAttribute(gemm_mma<1>, cudaFuncAttributeMaxDynamicSharedMemorySize, SMEM_TOTAL);

    // 1) round inputs/weights to tf32 (zero-mean quantization error)
    round_copy<<<2048, 256>>>(x,  0, (size_t)E_ * M_ * KDIM / 4);
    round_copy<<<2048, 256>>>(w1, 1, (size_t)E_ * KDIM * I2_ / 4);
    round_copy<<<2048, 256>>>(w2, 2, (size_t)E_ * IN_ * H_ / 4);

    // 2) GEMM1 + bias + SwiGLU -> g_act
    gemm_mma<0><<<dim3(I2_ / TN, M_ / TM, E_), 256, SMEM_TOTAL>>>(b1, nullptr);
    // 3) GEMM2 + bias -> out
    gemm_mma<1><<<dim3(H_ / TN, M_ / TM, E_), 256, SMEM_TOTAL>>>(b2, out);
}

// round 11
// speedup vs baseline: 1.0043x; 1.0043x over previous
#include <cuda_runtime.h>
#include <cstdint>

// ============================ problem constants ============================
static constexpr int E_  = 8;
static constexpr int M_  = 1024;
static constexpr int H_  = 2048;   // K of GEMM1, N of GEMM2
static constexpr int I2_ = 4096;   // w1 out cols (gate/up interleaved)
static constexpr int IN_ = 2048;   // intermediate = I2/2 = K of GEMM2
static constexpr int KDIM = 2048;  // K of both GEMMs

static constexpr int TM = 128, TN = 128, KC = 32;
static constexpr int NSTG = 3;
static constexpr int NIT = KDIM / KC;          // 64

// SMEM float strides:
//  A[m][k]  stride 36: ldmatrix row-chunks land in distinct 16B banks per 8-row phase
//  B[k][n]  stride 136: bank = (8k + n) % 32 -> unique over (l4, g) for scalar LDS
static constexpr int ASTR = 36;
static constexpr int BSTR = 136;
static constexpr int A_FLOATS = TM * ASTR;     // 4608
static constexpr int B_FLOATS = KC * BSTR;     // 4352
static constexpr int STGF = A_FLOATS + B_FLOATS;          // 8960 floats
static constexpr int SMEM_TOTAL = NSTG * STGF * 4;        // 107520 B

// ============================ device scratch ============================
__device__ float g_act[E_ * M_ * IN_];    // activation fp32  [e][m][i]

// ============================ helpers ============================
__device__ __forceinline__ uint32_t smem_u32(const void* p) {
    uint32_t a;
    asm("{ .reg .u64 t; cvta.to.shared.u64 t, %1; cvt.u32.u64 %0, t; }" : "=r"(a) : "l"(p));
    return a;
}

// in-register fp32 -> tf32 round-to-nearest (bits stay in a b32 reg)
__device__ __forceinline__ uint32_t cvt_tf32(uint32_t x) {
    uint32_t y;
    asm("cvt.rna.tf32.f32 %0, %1;" : "=r"(y) : "r"(x));
    return y;
}

__device__ __forceinline__ void cpa16(uint32_t s, const float* g) {
    asm volatile("cp.async.cg.shared.global [%0], [%1], 16;" :: "r"(s), "l"(g));
}
#define CP_COMMIT() asm volatile("cp.async.commit_group;" ::: "memory")
#define CP_WAIT1()  asm volatile("cp.async.wait_group 1;" ::: "memory")

__device__ __forceinline__ void ldsm_x4(uint32_t& r0, uint32_t& r1,
                                        uint32_t& r2, uint32_t& r3, uint32_t addr) {
    asm volatile("ldmatrix.sync.aligned.m8n8.x4.shared.b16 {%0,%1,%2,%3}, [%4];"
                 : "=r"(r0), "=r"(r1), "=r"(r2), "=r"(r3) : "r"(addr));
}

// m16n8k8 tf32 MMA, D += A*B
__device__ __forceinline__ void mma8(float* d, const uint32_t* a, const uint32_t* b) {
    asm volatile(
        "mma.sync.aligned.m16n8k8.row.col.f32.tf32.tf32.f32 "
        "{%0,%1,%2,%3},{%4,%5,%6,%7},{%8,%9},{%0,%1,%2,%3};"
        : "+f"(d[0]), "+f"(d[1]), "+f"(d[2]), "+f"(d[3])
        : "r"(a[0]), "r"(a[1]), "r"(a[2]), "r"(a[3]), "r"(b[0]), "r"(b[1]));
}

__device__ __forceinline__ float swiglu(float gate, float up) {
    gate = fminf(gate, 7.0f);
    up   = fminf(fmaxf(up, -7.0f), 7.0f);
    float glu = gate * (1.0f / (1.0f + __expf(-1.702f * gate)));
    return (up + 1.0f) * glu;
}

// ============================ GEMM ============================
// MODE 0: act = swiglu(X @ w1 + b1)  -> g_act   (N total = 4096)
// MODE 1: out = act @ w2 + b2                    (N total = 2048)
template <int MODE>
__global__ __launch_bounds__(256) void gemm_mma(const float* __restrict__ Ag,
                                                const float* __restrict__ Bg,
                                                const float* __restrict__ bias,
                                                float* __restrict__ outp) {
    constexpr int NTOT = (MODE == 0) ? I2_ : H_;
    extern __shared__ __align__(16) float sm[];
    const uint32_t sb = smem_u32(sm);

    const int tid = threadIdx.x;
    const int wid = tid >> 5, lane = tid & 31;
    const int wm = wid >> 2, wn = wid & 3;     // 2 x 4 warp grid
    const int g = lane >> 2, l4 = lane & 3;
    const int e = blockIdx.z;
    const int m0 = blockIdx.y * TM, n0 = blockIdx.x * TN;

    const float* Ae = Ag + (size_t)e * M_ * KDIM;
    const float* Be = Bg + (size_t)e * KDIM * NTOT;

    float acc[4][4][4] = {};

    // cp.async chunk coordinates
    const int ar = tid >> 3, ac = (tid & 7) * 4;     // A: 8 chunks/row
    const int br = tid >> 5, bc = (tid & 31) * 4;    // B: 32 chunks/row

    // ldmatrix per-thread address pieces: row = wm*64 + mt*16 + (lane&15),
    // 16B-chunk within row = 2*ks + (lane>>4)
    const int lrow = wm * 64 + (lane & 15);
    const int lchk = lane >> 4;

    auto load_stage = [&](int s, int k0) {
        uint32_t abase = sb + (uint32_t)(s * STGF) * 4u;
        uint32_t bbase = abase + (uint32_t)A_FLOATS * 4u;
#pragma unroll
        for (int p = 0; p < 4; p++) {
            int r = ar + p * 32;
            cpa16(abase + (uint32_t)(r * ASTR + ac) * 4u,
                  Ae + (size_t)(m0 + r) * KDIM + k0 + ac);
        }
#pragma unroll
        for (int p = 0; p < 4; p++) {
            int r = br + p * 8;
            cpa16(bbase + (uint32_t)(r * BSTR + bc) * 4u,
                  Be + (size_t)(k0 + r) * NTOT + n0 + bc);
        }
    };

    // prologue: stages 0 and 1
    load_stage(0, 0);      CP_COMMIT();
    load_stage(1, KC);     CP_COMMIT();

    for (int i = 0; i < NIT; i++) {
        CP_WAIT1();              // stage i resident
        __syncthreads();
        if (i + 2 < NIT) { load_stage((i + 2) % NSTG, (i + 2) * KC); }
        CP_COMMIT();

        const uint32_t As_addr = sb + (uint32_t)((i % NSTG) * STGF) * 4u;
        const float* Bs = sm + (i % NSTG) * STGF + A_FLOATS;

#pragma unroll
        for (int ks = 0; ks < 4; ks++) {
            const int k = ks * 8;
            uint32_t af[4][4], bf[4][2];
#pragma unroll
            for (int mt = 0; mt < 4; mt++) {
                uint32_t addr = As_addr +
                    (uint32_t)((lrow + mt * 16) * ASTR + (2 * ks + lchk) * 4) * 4u;
                ldsm_x4(af[mt][0], af[mt][1], af[mt][2], af[mt][3], addr);
            }
#pragma unroll
            for (int nt = 0; nt < 4; nt++) {
                int c = wn * 32 + nt * 8 + g;
                bf[nt][0] = __float_as_uint(Bs[(k + l4) * BSTR + c]);
                bf[nt][1] = __float_as_uint(Bs[(k + l4 + 4) * BSTR + c]);
            }
#pragma unroll
            for (int mt = 0; mt < 4; mt++)
#pragma unroll
                for (int q = 0; q < 4; q++) af[mt][q] = cvt_tf32(af[mt][q]);
#pragma unroll
            for (int nt = 0; nt < 4; nt++) {
                bf[nt][0] = cvt_tf32(bf[nt][0]);
                bf[nt][1] = cvt_tf32(bf[nt][1]);
            }
#pragma unroll
            for (int mt = 0; mt < 4; mt++)
#pragma unroll
                for (int nt = 0; nt < 4; nt++)
                    mma8(acc[mt][nt], af[mt], bf[nt]);
        }
    }

    // ============================ epilogue ============================
#pragma unroll
    for (int mt = 0; mt < 4; mt++) {
#pragma unroll
        for (int nt = 0; nt < 4; nt++) {
            int mrow = m0 + wm * 64 + mt * 16 + g;
            int ncol = n0 + wn * 32 + nt * 8 + 2 * l4;
            float2 bv = *(const float2*)&bias[(size_t)e * NTOT + ncol];
            if (MODE == 0) {
                // (even, odd) col pair = (gate, up)
                float a0 = swiglu(acc[mt][nt][0] + bv.x, acc[mt][nt][1] + bv.y);
                float a1 = swiglu(acc[mt][nt][2] + bv.x, acc[mt][nt][3] + bv.y);
                int io = ncol >> 1;
                g_act[((size_t)e * M_ + mrow)     * IN_ + io] = a0;
                g_act[((size_t)e * M_ + mrow + 8) * IN_ + io] = a1;
            } else {
                float2 v0 = make_float2(acc[mt][nt][0] + bv.x, acc[mt][nt][1] + bv.y);
                float2 v1 = make_float2(acc[mt][nt][2] + bv.x, acc[mt][nt][3] + bv.y);
                *(float2*)&outp[((size_t)e * M_ + mrow)     * H_ + ncol] = v0;
                *(float2*)&outp[((size_t)e * M_ + mrow + 8) * H_ + ncol] = v1;
            }
        }
    }
}

// ============================ launch ============================
extern "C" void kernel_launch(void* const* d_in, const int* in_sizes, int n_in,
                              void* d_out, int out_size) {
    const float* x  = (const float*)d_in[0];
    const float* w1 = (const float*)d_in[1];
    const float* b1 = (const float*)d_in[2];
    const float* w2 = (const float*)d_in[3];
    const float* b2 = (const float*)d_in[4];
    float* out = (float*)d_out;

    cudaFuncSetAttribute(gemm_mma<0>, cudaFuncAttributeMaxDynamicSharedMemorySize, SMEM_TOTAL);
    cudaFuncSetAttribute(gemm_mma<1>, cudaFuncAttributeMaxDynamicSharedMemorySize, SMEM_TOTAL);

    float* actp;
    cudaGetSymbolAddress((void**)&actp, g_act);

    // GEMM1 + bias + SwiGLU -> g_act   (reads x, w1 directly; tf32 rounding in-register)
    gemm_mma<0><<<dim3(I2_ / TN, M_ / TM, E_), 256, SMEM_TOTAL>>>(x, w1, b1, nullptr);
    // GEMM2 + bias -> out
    gemm_mma<1><<<dim3(H_ / TN, M_ / TM, E_), 256, SMEM_TOTAL>>>(actp, w2, b2, out);
}

// round 12
// speedup vs baseline: 1.0807x; 1.0760x over previous
#include <cuda_runtime.h>
#include <cstdint>

// ============================ problem constants ============================
static constexpr int E_  = 8;
static constexpr int M_  = 1024;
static constexpr int H_  = 2048;   // K of GEMM1, N of GEMM2
static constexpr int I2_ = 4096;   // w1 out cols (gate/up interleaved)
static constexpr int IN_ = 2048;   // intermediate = I2/2 = K of GEMM2
static constexpr int KDIM = 2048;  // K of both GEMMs

static constexpr int TM = 128, TN = 128, KC = 32;
static constexpr int NSTG = 3;
static constexpr int NIT = KDIM / KC;          // 64

// Both tiles [128 rows][32 k-floats], row stride 36 floats.
// ldmatrix phase conflict-freedom: 16B-chunk index = (9*row + chunk) mod 8,
// distinct for any 8 consecutive rows at fixed chunk.
static constexpr int TSTR = 36;
static constexpr int T_FLOATS = 128 * TSTR;              // 4608
static constexpr int STGF = 2 * T_FLOATS;                // 9216 floats (A + B)
static constexpr int SMEM_TOTAL = NSTG * STGF * 4;       // 110592 B (2 CTAs = 221KB/SM)

// ============================ device scratch ============================
__device__ float g_xr [E_ * M_  * KDIM];   // tf32-rounded X       [e][m][k]
__device__ float g_w1t[E_ * I2_ * KDIM];   // tf32 w1 transposed   [e][n][k]
__device__ float g_w2t[E_ * H_  * IN_ ];   // tf32 w2 transposed   [e][n][k]
__device__ float g_act[E_ * M_  * IN_ ];   // tf32 activation      [e][m][i]

// ============================ helpers ============================
__device__ __forceinline__ uint32_t smem_u32(const void* p) {
    uint32_t a;
    asm("{ .reg .u64 t; cvta.to.shared.u64 t, %1; cvt.u32.u64 %0, t; }" : "=r"(a) : "l"(p));
    return a;
}

// fp32 -> tf32 round-to-nearest (HW), bits in b32
__device__ __forceinline__ float rtf32(float x) {
    uint32_t y;
    asm("cvt.rna.tf32.f32 %0, %1;" : "=r"(y) : "r"(__float_as_uint(x)));
    return __uint_as_float(y);
}

__device__ __forceinline__ void cpa16(uint32_t s, const float* g) {
    asm volatile("cp.async.cg.shared.global [%0], [%1], 16;" :: "r"(s), "l"(g));
}
#define CP_COMMIT() asm volatile("cp.async.commit_group;" ::: "memory")
#define CP_WAIT1()  asm volatile("cp.async.wait_group 1;" ::: "memory")

__device__ __forceinline__ void ldsm_x4(uint32_t& r0, uint32_t& r1,
                                        uint32_t& r2, uint32_t& r3, uint32_t addr) {
    asm volatile("ldmatrix.sync.aligned.m8n8.x4.shared.b16 {%0,%1,%2,%3}, [%4];"
                 : "=r"(r0), "=r"(r1), "=r"(r2), "=r"(r3) : "r"(addr));
}

// m16n8k8 tf32 MMA, D += A*B
__device__ __forceinline__ void mma8(float* d, const uint32_t* a, const uint32_t* b) {
    asm volatile(
        "mma.sync.aligned.m16n8k8.row.col.f32.tf32.tf32.f32 "
        "{%0,%1,%2,%3},{%4,%5,%6,%7},{%8,%9},{%0,%1,%2,%3};"
        : "+f"(d[0]), "+f"(d[1]), "+f"(d[2]), "+f"(d[3])
        : "r"(a[0]), "r"(a[1]), "r"(a[2]), "r"(a[3]), "r"(b[0]), "r"(b[1]));
}

__device__ __forceinline__ float swiglu(float gate, float up) {
    gate = fminf(gate, 7.0f);
    up   = fminf(fmaxf(up, -7.0f), 7.0f);
    float glu = gate * (1.0f / (1.0f + __expf(-1.702f * gate)));
    return (up + 1.0f) * glu;
}

// ============================ prep kernels ============================
__global__ __launch_bounds__(256) void round_x(const float* __restrict__ src) {
    size_t n4 = (size_t)E_ * M_ * KDIM / 4;
    const float4* s4 = (const float4*)src;
    float4* d4 = (float4*)g_xr;
    for (size_t i = (size_t)blockIdx.x * blockDim.x + threadIdx.x; i < n4;
         i += (size_t)gridDim.x * blockDim.x) {
        float4 v = s4[i];
        v.x = rtf32(v.x); v.y = rtf32(v.y); v.z = rtf32(v.z); v.w = rtf32(v.w);
        d4[i] = v;
    }
}

// dst[e][c][r] = rtf32(src[e][r][c]);  sel 0 -> g_w1t, sel 1 -> g_w2t
__global__ __launch_bounds__(256) void transpose_rt(const float* __restrict__ src,
                                                    int sel, int R, int C) {
    __shared__ float t[32][33];
    int e = blockIdx.z;
    const float* s = src + (size_t)e * R * C;
    float* d = (sel == 0 ? g_w1t : g_w2t) + (size_t)e * R * C;
    int c0 = blockIdx.x * 32, r0 = blockIdx.y * 32;
    int tx = threadIdx.x, ty = threadIdx.y;
#pragma unroll
    for (int i = 0; i < 32; i += 8)
        t[ty + i][tx] = s[(size_t)(r0 + ty + i) * C + c0 + tx];
    __syncthreads();
#pragma unroll
    for (int i = 0; i < 32; i += 8)
        d[(size_t)(c0 + ty + i) * R + r0 + tx] = rtf32(t[tx][ty + i]);
}

// ============================ GEMM ============================
// MODE 0: act = swiglu(X @ w1 + b1) -> g_act   (N total = 4096; B = g_w1t [n][k])
// MODE 1: out = act @ w2 + b2                   (N total = 2048; B = g_w2t [n][k])
template <int MODE>
__global__ __launch_bounds__(256, 2) void gemm_mma(const float* __restrict__ Ag,
                                                   const float* __restrict__ Bg,
                                                   const float* __restrict__ bias,
                                                   float* __restrict__ outp) {
    constexpr int NTOT = (MODE == 0) ? I2_ : H_;
    extern __shared__ __align__(16) float sm[];
    const uint32_t sb = smem_u32(sm);

    const int tid = threadIdx.x;
    const int wid = tid >> 5, lane = tid & 31;
    const int wm = wid >> 2, wn = wid & 3;     // 2 x 4 warp grid
    const int g = lane >> 2, l4 = lane & 3;
    const int e = blockIdx.z;
    const int m0 = blockIdx.y * TM, n0 = blockIdx.x * TN;

    const float* Ae = Ag + (size_t)e * M_ * KDIM;
    const float* Be = Bg + (size_t)e * NTOT * KDIM;   // [n][k]

    float acc[4][4][4] = {};

    // cp.async chunk coordinates (identical pattern for A and B tiles)
    const int cr = tid >> 3, cc = (tid & 7) * 4;     // rows 0..31(+32p), 8 chunks/row

    // ldmatrix A: row = wm*64 + mt*16 + (lane&15), chunk = 2*ks + (lane>>4)
    const int a_row = wm * 64 + (lane & 15);
    const int a_chk = lane >> 4;
    // ldmatrix B: row = wn*32 + p*16 + ((lane>>4)*8) + (lane&7), chunk = 2*ks + ((lane>>3)&1)
    const int b_row = wn * 32 + ((lane >> 4) * 8) + (lane & 7);
    const int b_chk = (lane >> 3) & 1;

    auto load_stage = [&](int s, int k0) {
        uint32_t abase = sb + (uint32_t)(s * STGF) * 4u;
        uint32_t bbase = abase + (uint32_t)T_FLOATS * 4u;
#pragma unroll
        for (int p = 0; p < 4; p++) {
            int r = cr + p * 32;
            cpa16(abase + (uint32_t)(r * TSTR + cc) * 4u,
                  Ae + (size_t)(m0 + r) * KDIM + k0 + cc);
        }
#pragma unroll
        for (int p = 0; p < 4; p++) {
            int r = cr + p * 32;
            cpa16(bbase + (uint32_t)(r * TSTR + cc) * 4u,
                  Be + (size_t)(n0 + r) * KDIM + k0 + cc);
        }
    };

    // prologue: stages 0 and 1
    load_stage(0, 0);      CP_COMMIT();
    load_stage(1, KC);     CP_COMMIT();

    for (int i = 0; i < NIT; i++) {
        CP_WAIT1();              // stage i resident
        __syncthreads();
        if (i + 2 < NIT) { load_stage((i + 2) % NSTG, (i + 2) * KC); }
        CP_COMMIT();

        const uint32_t As_addr = sb + (uint32_t)((i % NSTG) * STGF) * 4u;
        const uint32_t Bs_addr = As_addr + (uint32_t)T_FLOATS * 4u;

#pragma unroll
        for (int ks = 0; ks < 4; ks++) {
            uint32_t af[4][4], bf[4][2];
#pragma unroll
            for (int mt = 0; mt < 4; mt++) {
                uint32_t addr = As_addr +
                    (uint32_t)((a_row + mt * 16) * TSTR + (2 * ks + a_chk) * 4) * 4u;
                ldsm_x4(af[mt][0], af[mt][1], af[mt][2], af[mt][3], addr);
            }
#pragma unroll
            for (int p = 0; p < 2; p++) {   // nt pairs (0,1) and (2,3)
                uint32_t addr = Bs_addr +
                    (uint32_t)((b_row + p * 16) * TSTR + (2 * ks + b_chk) * 4) * 4u;
                ldsm_x4(bf[2 * p][0], bf[2 * p][1], bf[2 * p + 1][0], bf[2 * p + 1][1], addr);
            }
#pragma unroll
            for (int mt = 0; mt < 4; mt++)
#pragma unroll
                for (int nt = 0; nt < 4; nt++)
                    mma8(acc[mt][nt], af[mt], bf[nt]);
        }
    }

    // ============================ epilogue ============================
#pragma unroll
    for (int mt = 0; mt < 4; mt++) {
#pragma unroll
        for (int nt = 0; nt < 4; nt++) {
            int mrow = m0 + wm * 64 + mt * 16 + g;
            int ncol = n0 + wn * 32 + nt * 8 + 2 * l4;
            float2 bv = *(const float2*)&bias[(size_t)e * NTOT + ncol];
            if (MODE == 0) {
                // (even, odd) col pair = (gate, up); store tf32-rounded act
                float a0 = swiglu(acc[mt][nt][0] + bv.x, acc[mt][nt][1] + bv.y);
                float a1 = swiglu(acc[mt][nt][2] + bv.x, acc[mt][nt][3] + bv.y);
                int io = ncol >> 1;
                g_act[((size_t)e * M_ + mrow)     * IN_ + io] = rtf32(a0);
                g_act[((size_t)e * M_ + mrow + 8) * IN_ + io] = rtf32(a1);
            } else {
                float2 v0 = make_float2(acc[mt][nt][0] + bv.x, acc[mt][nt][1] + bv.y);
                float2 v1 = make_float2(acc[mt][nt][2] + bv.x, acc[mt][nt][3] + bv.y);
                *(float2*)&outp[((size_t)e * M_ + mrow)     * H_ + ncol] = v0;
                *(float2*)&outp[((size_t)e * M_ + mrow + 8) * H_ + ncol] = v1;
            }
        }
    }
}

// ============================ launch ============================
extern "C" void kernel_launch(void* const* d_in, const int* in_sizes, int n_in,
                              void* d_out, int out_size) {
    const float* x  = (const float*)d_in[0];
    const float* w1 = (const float*)d_in[1];
    const float* b1 = (const float*)d_in[2];
    const float* w2 = (const float*)d_in[3];
    const float* b2 = (const float*)d_in[4];
    float* out = (float*)d_out;

    cudaFuncSetAttribute(gemm_mma<0>, cudaFuncAttributeMaxDynamicSharedMemorySize, SMEM_TOTAL);
    cudaFuncSetAttribute(gemm_mma<1>, cudaFuncAttributeMaxDynamicSharedMemorySize, SMEM_TOTAL);

    float* actp;
    cudaGetSymbolAddress((void**)&actp, g_act);
    float* w1tp;
    cudaGetSymbolAddress((void**)&w1tp, g_w1t);
    float* w2tp;
    cudaGetSymbolAddress((void**)&w2tp, g_w2t);
    float* xrp;
    cudaGetSymbolAddress((void**)&xrp, g_xr);

    // prep: round x; transpose+round w1 -> [n][k], w2 -> [n][k]
    round_x<<<1024, 256>>>(x);
    transpose_rt<<<dim3(I2_ / 32, H_ / 32, E_), dim3(32, 8)>>>(w1, 0, H_, I2_);
    transpose_rt<<<dim3(H_ / 32, IN_ / 32, E_), dim3(32, 8)>>>(w2, 1, IN_, H_);

    // GEMM1 + bias + SwiGLU -> g_act
    gemm_mma<0><<<dim3(I2_ / TN, M_ / TM, E_), 256, SMEM_TOTAL>>>(xrp, w1tp, b1, nullptr);
    // GEMM2 + bias -> out
    gemm_mma<1><<<dim3(H_ / TN, M_ / TM, E_), 256, SMEM_TOTAL>>>(actp, w2tp, b2, out);
}